// round 2
// baseline (speedup 1.0000x reference)
#include <cuda_runtime.h>

#define N_NODES 100000
#define N_EDGES 1600000
#define D 256
#define NEG_SLOPE 0.01f

// ---------------- device scratch (static; no runtime allocation) ----------------
__device__ float g_side[(size_t)N_NODES * D];   // SpMM result, 102.4 MB
__device__ int   g_cnt[N_NODES];                // per-row edge counts
__device__ int   g_off[N_NODES + 1];            // exclusive scan (CSR offsets)
__device__ int   g_cur[N_NODES];                // scatter cursors
__device__ int   g_scol[N_EDGES];               // cols sorted by row
__device__ float g_sval[N_EDGES];               // vals sorted by row

// ---------------- 1. zero counters ----------------
__global__ void k_zero_cnt() {
    int i = blockIdx.x * blockDim.x + threadIdx.x;
    if (i < N_NODES) g_cnt[i] = 0;
}

// ---------------- 2. histogram rows ----------------
__global__ void k_hist(const int* __restrict__ rows) {
    int e = blockIdx.x * blockDim.x + threadIdx.x;
    if (e < N_EDGES) atomicAdd(&g_cnt[rows[e]], 1);
}

// ---------------- 3. single-block exclusive scan (shfl-based) ----------------
__global__ void k_scan() {
    __shared__ int warp_sums[32];
    __shared__ int s_carry;
    const int T = 1024;
    int tid = threadIdx.x;
    int lane = tid & 31;
    int wid = tid >> 5;
    if (tid == 0) s_carry = 0;
    __syncthreads();

    for (int base = 0; base < N_NODES; base += T) {
        int idx = base + tid;
        int x = (idx < N_NODES) ? g_cnt[idx] : 0;
        // inclusive warp scan
        int v = x;
        #pragma unroll
        for (int off = 1; off < 32; off <<= 1) {
            int t = __shfl_up_sync(0xFFFFFFFFu, v, off);
            if (lane >= off) v += t;
        }
        if (lane == 31) warp_sums[wid] = v;
        __syncthreads();
        if (wid == 0) {
            int w = warp_sums[lane];
            #pragma unroll
            for (int off = 1; off < 32; off <<= 1) {
                int t = __shfl_up_sync(0xFFFFFFFFu, w, off);
                if (lane >= off) w += t;
            }
            warp_sums[lane] = w;   // inclusive warp prefix
        }
        __syncthreads();
        int carry = s_carry;
        int warp_prefix = (wid > 0) ? warp_sums[wid - 1] : 0;
        int incl = v + warp_prefix;
        int excl = incl - x + carry;
        if (idx < N_NODES) { g_off[idx] = excl; g_cur[idx] = excl; }
        __syncthreads();                       // everyone done reading carry/warp_sums
        if (tid == T - 1) s_carry = carry + incl;  // chunk total
        __syncthreads();
    }
    if (tid == 0) g_off[N_NODES] = s_carry;    // == N_EDGES
}

// ---------------- 4. scatter edges into row-sorted order ----------------
__global__ void k_scatter(const int* __restrict__ rows, const int* __restrict__ cols,
                          const float* __restrict__ vals) {
    int e = blockIdx.x * blockDim.x + threadIdx.x;
    if (e < N_EDGES) {
        int r = rows[e];
        int p = atomicAdd(&g_cur[r], 1);
        g_scol[p] = cols[e];
        g_sval[p] = vals[e];
    }
}

// ---------------- 5. atomic-free SpMM: one block per row ----------------
__global__ __launch_bounds__(256) void k_spmm(const float* __restrict__ ego) {
    int r = blockIdx.x;
    int t = threadIdx.x;              // 0..255, one output element each
    int beg = g_off[r];
    int end = g_off[r + 1];

    float acc = 0.f;
    // 2-stage software pipeline to hide L2 gather latency
    int i = beg;
    float v = 0.f, e = 0.f;
    if (i < end) {
        int c = g_scol[i];
        v = g_sval[i];
        e = __ldg(&ego[(size_t)c * D + t]);
    }
    while (i < end) {
        int j = i + 1;
        float v2 = 0.f, e2 = 0.f;
        if (j < end) {
            int c2 = g_scol[j];
            v2 = g_sval[j];
            e2 = __ldg(&ego[(size_t)c2 * D + t]);
        }
        acc = fmaf(v, e, acc);
        v = v2; e = e2; i = j;
    }
    g_side[(size_t)r * D + t] = acc;
}

// ---------------- 6. fused elementwise + dual GEMM + leakyrelu + add ----------------
#define BM 64
#define BN 64
#define BK 16

__global__ __launch_bounds__(256) void k_gemm(
    const float* __restrict__ ego,
    const float* __restrict__ W1, const float* __restrict__ b1,
    const float* __restrict__ W2, const float* __restrict__ b2,
    float* __restrict__ out)
{
    // A tiles stored transposed [k][m] so inner-loop A reads are float4
    __shared__ __align__(16) float Us[BK][BM + 4];
    __shared__ __align__(16) float Vs[BK][BM + 4];
    __shared__ __align__(16) float W1s[BK][BN];
    __shared__ __align__(16) float W2s[BK][BN];

    int tid = threadIdx.x;
    int tx = tid & 15;            // n-group
    int ty = tid >> 4;            // m-group
    int m0 = ty * 4;
    int n0 = tx * 4;
    int bm = blockIdx.x * BM;
    int bn = blockIdx.y * BN;

    float acc1[4][4], acc2[4][4];
    #pragma unroll
    for (int i = 0; i < 4; i++)
        #pragma unroll
        for (int j = 0; j < 4; j++) { acc1[i][j] = 0.f; acc2[i][j] = 0.f; }

    // A-tile loader mapping: 256 threads cover 64 rows x 4 float4 (16 k)
    int lrow = tid >> 2;              // 0..63
    int lk4  = (tid & 3) * 4;         // 0,4,8,12
    int grow = bm + lrow;
    bool rowok = (grow < N_NODES);
    // W-tile loader mapping: 16 k-rows x 16 float4
    int wk  = tid >> 4;               // 0..15
    int wn4 = (tid & 15) * 4;         // 0..60

    for (int k0 = 0; k0 < D; k0 += BK) {
        float4 e4 = make_float4(0.f, 0.f, 0.f, 0.f);
        float4 s4 = make_float4(0.f, 0.f, 0.f, 0.f);
        if (rowok) {
            e4 = *(const float4*)&ego[(size_t)grow * D + k0 + lk4];
            s4 = *(const float4*)&g_side[(size_t)grow * D + k0 + lk4];
        }
        // transposed stores (scalar, load phase only)
        Us[lk4 + 0][lrow] = e4.x + s4.x;
        Us[lk4 + 1][lrow] = e4.y + s4.y;
        Us[lk4 + 2][lrow] = e4.z + s4.z;
        Us[lk4 + 3][lrow] = e4.w + s4.w;
        Vs[lk4 + 0][lrow] = e4.x * s4.x;
        Vs[lk4 + 1][lrow] = e4.y * s4.y;
        Vs[lk4 + 2][lrow] = e4.z * s4.z;
        Vs[lk4 + 3][lrow] = e4.w * s4.w;

        float4 w1 = *(const float4*)&W1[(size_t)(k0 + wk) * D + bn + wn4];
        float4 w2 = *(const float4*)&W2[(size_t)(k0 + wk) * D + bn + wn4];
        *(float4*)&W1s[wk][wn4] = w1;
        *(float4*)&W2s[wk][wn4] = w2;

        __syncthreads();

        #pragma unroll
        for (int kk = 0; kk < BK; kk++) {
            float4 au4 = *(const float4*)&Us[kk][m0];
            float4 av4 = *(const float4*)&Vs[kk][m0];
            float4 bu4 = *(const float4*)&W1s[kk][n0];
            float4 bv4 = *(const float4*)&W2s[kk][n0];
            float au[4] = {au4.x, au4.y, au4.z, au4.w};
            float av[4] = {av4.x, av4.y, av4.z, av4.w};
            float bu[4] = {bu4.x, bu4.y, bu4.z, bu4.w};
            float bv[4] = {bv4.x, bv4.y, bv4.z, bv4.w};
            #pragma unroll
            for (int i = 0; i < 4; i++) {
                #pragma unroll
                for (int j = 0; j < 4; j++) {
                    acc1[i][j] = fmaf(au[i], bu[j], acc1[i][j]);
                    acc2[i][j] = fmaf(av[i], bv[j], acc2[i][j]);
                }
            }
        }
        __syncthreads();
    }

    // epilogue: out = lrelu(acc1+b1) + lrelu(acc2+b2); lrelu(x) = max(x, 0.01x)
    float4 bb1 = *(const float4*)&b1[bn + n0];
    float4 bb2 = *(const float4*)&b2[bn + n0];
    float b1a[4] = {bb1.x, bb1.y, bb1.z, bb1.w};
    float b2a[4] = {bb2.x, bb2.y, bb2.z, bb2.w};

    #pragma unroll
    for (int i = 0; i < 4; i++) {
        int gm = bm + m0 + i;
        if (gm < N_NODES) {
            float4 o;
            float* op = (float*)&o;
            #pragma unroll
            for (int j = 0; j < 4; j++) {
                float x1 = acc1[i][j] + b1a[j];
                float x2 = acc2[i][j] + b2a[j];
                x1 = fmaxf(x1, NEG_SLOPE * x1);
                x2 = fmaxf(x2, NEG_SLOPE * x2);
                op[j] = x1 + x2;
            }
            *(float4*)&out[(size_t)gm * D + bn + n0] = o;
        }
    }
}

// ---------------- launch ----------------
extern "C" void kernel_launch(void* const* d_in, const int* in_sizes, int n_in,
                              void* d_out, int out_size) {
    const float* ego  = (const float*)d_in[0];
    const float* vals = (const float*)d_in[1];
    const float* W1   = (const float*)d_in[2];
    const float* b1   = (const float*)d_in[3];
    const float* W2   = (const float*)d_in[4];
    const float* b2   = (const float*)d_in[5];
    const int*   rows = (const int*)d_in[6];
    const int*   cols = (const int*)d_in[7];
    float*       out  = (float*)d_out;

    k_zero_cnt<<<(N_NODES + 255) / 256, 256>>>();
    k_hist<<<(N_EDGES + 255) / 256, 256>>>(rows);
    k_scan<<<1, 1024>>>();
    k_scatter<<<(N_EDGES + 255) / 256, 256>>>(rows, cols, vals);
    k_spmm<<<N_NODES, 256>>>(ego);

    dim3 g((N_NODES + BM - 1) / BM, D / BN);
    k_gemm<<<g, 256>>>(ego, W1, b1, W2, b2, out);
}

// round 5
// speedup vs baseline: 1.5137x; 1.5137x over previous
#include <cuda_runtime.h>
#include <cuda_bf16.h>
#include <cstdint>

#define N_NODES 100000
#define N_EDGES 1600000
#define D 256
#define NEG_SLOPE 0.01f

// ================= device scratch =================
__device__ int   g_cnt[N_NODES];
__device__ int   g_off[N_NODES + 1];
__device__ int   g_cur[N_NODES];
__device__ int   g_scol[N_EDGES];
__device__ float g_sval[N_EDGES];
// bf16 hi/lo splits of U = ego+side, V = ego*side   [N_NODES][256] row-major
__device__ __nv_bfloat16 g_uhi[(size_t)N_NODES * D];
__device__ __nv_bfloat16 g_ulo[(size_t)N_NODES * D];
__device__ __nv_bfloat16 g_vhi[(size_t)N_NODES * D];
__device__ __nv_bfloat16 g_vlo[(size_t)N_NODES * D];
// W^T hi/lo splits, [n][k] row-major (k contiguous)
__device__ __nv_bfloat16 g_w1hi[D * D];
__device__ __nv_bfloat16 g_w1lo[D * D];
__device__ __nv_bfloat16 g_w2hi[D * D];
__device__ __nv_bfloat16 g_w2lo[D * D];

// ================= sort phase =================
__global__ void k_zero_cnt() {
    int i = blockIdx.x * blockDim.x + threadIdx.x;
    if (i < N_NODES) g_cnt[i] = 0;
}
__global__ void k_hist(const int* __restrict__ rows) {
    int e = blockIdx.x * blockDim.x + threadIdx.x;
    if (e < N_EDGES) atomicAdd(&g_cnt[rows[e]], 1);
}
__global__ void k_scan() {
    __shared__ int warp_sums[32];
    __shared__ int s_carry;
    const int T = 1024;
    int tid = threadIdx.x, lane = tid & 31, wid = tid >> 5;
    if (tid == 0) s_carry = 0;
    __syncthreads();
    for (int base = 0; base < N_NODES; base += T) {
        int idx = base + tid;
        int x = (idx < N_NODES) ? g_cnt[idx] : 0;
        int v = x;
        #pragma unroll
        for (int off = 1; off < 32; off <<= 1) {
            int t = __shfl_up_sync(0xFFFFFFFFu, v, off);
            if (lane >= off) v += t;
        }
        if (lane == 31) warp_sums[wid] = v;
        __syncthreads();
        if (wid == 0) {
            int w = warp_sums[lane];
            #pragma unroll
            for (int off = 1; off < 32; off <<= 1) {
                int t = __shfl_up_sync(0xFFFFFFFFu, w, off);
                if (lane >= off) w += t;
            }
            warp_sums[lane] = w;
        }
        __syncthreads();
        int carry = s_carry;
        int warp_prefix = (wid > 0) ? warp_sums[wid - 1] : 0;
        int incl = v + warp_prefix;
        int excl = incl - x + carry;
        if (idx < N_NODES) { g_off[idx] = excl; g_cur[idx] = excl; }
        __syncthreads();
        if (tid == T - 1) s_carry = carry + incl;
        __syncthreads();
    }
    if (tid == 0) g_off[N_NODES] = s_carry;
}
__global__ void k_scatter(const int* __restrict__ rows, const int* __restrict__ cols,
                          const float* __restrict__ vals) {
    int e = blockIdx.x * blockDim.x + threadIdx.x;
    if (e < N_EDGES) {
        int r = rows[e];
        int p = atomicAdd(&g_cur[r], 1);
        g_scol[p] = cols[e];
        g_sval[p] = vals[e];
    }
}

// ================= SpMM + bi-interaction + bf16 split =================
__global__ __launch_bounds__(256) void k_spmm(const float* __restrict__ ego) {
    int r = blockIdx.x;
    int t = threadIdx.x;
    int beg = g_off[r], end = g_off[r + 1];

    float acc = 0.f;
    int i = beg;
    float v = 0.f, e = 0.f;
    if (i < end) {
        int c = g_scol[i];
        v = g_sval[i];
        e = __ldg(&ego[(size_t)c * D + t]);
    }
    while (i < end) {
        int j = i + 1;
        float v2 = 0.f, e2 = 0.f;
        if (j < end) {
            int c2 = g_scol[j];
            v2 = g_sval[j];
            e2 = __ldg(&ego[(size_t)c2 * D + t]);
        }
        acc = fmaf(v, e, acc);
        v = v2; e = e2; i = j;
    }
    float e0 = __ldg(&ego[(size_t)r * D + t]);
    float u = e0 + acc;
    float w = e0 * acc;
    __nv_bfloat16 uh = __float2bfloat16(u);
    __nv_bfloat16 wh = __float2bfloat16(w);
    size_t o = (size_t)r * D + t;
    g_uhi[o] = uh;
    g_ulo[o] = __float2bfloat16(u - __bfloat162float(uh));
    g_vhi[o] = wh;
    g_vlo[o] = __float2bfloat16(w - __bfloat162float(wh));
}

// ================= W transpose + split: g_w*[n][k] =================
__global__ void k_wprep(const float* __restrict__ W1, const float* __restrict__ W2) {
    int idx = blockIdx.x * blockDim.x + threadIdx.x;   // 65536
    int n = idx & 255, k = idx >> 8;
    float w1 = W1[k * D + n];
    float w2 = W2[k * D + n];
    __nv_bfloat16 h1 = __float2bfloat16(w1);
    __nv_bfloat16 h2 = __float2bfloat16(w2);
    int o = n * D + k;
    g_w1hi[o] = h1; g_w1lo[o] = __float2bfloat16(w1 - __bfloat162float(h1));
    g_w2hi[o] = h2; g_w2lo[o] = __float2bfloat16(w2 - __bfloat162float(h2));
}

// ================= mma.sync helpers =================
__device__ __forceinline__ uint32_t smem_u32(const void* p) {
    uint32_t a;
    asm("{ .reg .u64 t; cvta.to.shared.u64 t, %1; cvt.u32.u64 %0, t; }" : "=r"(a) : "l"(p));
    return a;
}
__device__ __forceinline__ void ldsm_x4(uint32_t* r, uint32_t addr) {
    asm volatile("ldmatrix.sync.aligned.m8n8.x4.shared.b16 {%0,%1,%2,%3}, [%4];"
        : "=r"(r[0]), "=r"(r[1]), "=r"(r[2]), "=r"(r[3]) : "r"(addr));
}
__device__ __forceinline__ void mma16816(float* d, const uint32_t* a, const uint32_t* b) {
    asm volatile("mma.sync.aligned.m16n8k16.row.col.f32.bf16.bf16.f32 "
        "{%0,%1,%2,%3}, {%4,%5,%6,%7}, {%8,%9}, {%0,%1,%2,%3};"
        : "+f"(d[0]), "+f"(d[1]), "+f"(d[2]), "+f"(d[3])
        : "r"(a[0]), "r"(a[1]), "r"(a[2]), "r"(a[3]), "r"(b[0]), "r"(b[1]));
}

// ================= tensor-core dual GEMM (mma.sync) =================
// CTA: M=128 x N=64, both GEMMs. 8 warps = 4(M) x 2(N), warp tile 32x32.
// SMEM: A tiles 128x64 bf16 x4 arrays, B tiles 64x64 bf16 x4 arrays; stride 72 bf16.
#define AST 72
#define E_UHI 0
#define E_ULO (128 * AST)
#define E_VHI (2 * 128 * AST)
#define E_VLO (3 * 128 * AST)
#define E_W1H (4 * 128 * AST)
#define E_W1L (E_W1H + 64 * AST)
#define E_W2H (E_W1H + 2 * 64 * AST)
#define E_W2L (E_W1H + 3 * 64 * AST)
#define SMEM_ELEMS (E_W1H + 4 * 64 * AST)          // 55296 bf16
#define SMEM_BYTES (SMEM_ELEMS * 2)                // 110592 B

__global__ __launch_bounds__(256) void k_gemm_mma(
    const float* __restrict__ b1, const float* __restrict__ b2,
    float* __restrict__ out)
{
    extern __shared__ __nv_bfloat16 sm[];
    uint32_t sb = smem_u32(sm);

    int tid = threadIdx.x;
    int lane = tid & 31;
    int wid = tid >> 5;
    int warp_m = wid >> 1;         // 0..3
    int warp_n = wid & 1;          // 0..1
    int bm = blockIdx.y * 128;
    int n0g = blockIdx.x * 64;

    float acc1[2][4][4], acc2[2][4][4];
    #pragma unroll
    for (int mt = 0; mt < 2; mt++)
        #pragma unroll
        for (int nt = 0; nt < 4; nt++)
            #pragma unroll
            for (int q = 0; q < 4; q++) { acc1[mt][nt][q] = 0.f; acc2[mt][nt][q] = 0.f; }

    const uint4* pUhi = (const uint4*)g_uhi;
    const uint4* pUlo = (const uint4*)g_ulo;
    const uint4* pVhi = (const uint4*)g_vhi;
    const uint4* pVlo = (const uint4*)g_vlo;
    const uint4* pW1h = (const uint4*)g_w1hi;
    const uint4* pW1l = (const uint4*)g_w1lo;
    const uint4* pW2h = (const uint4*)g_w2hi;
    const uint4* pW2l = (const uint4*)g_w2lo;
    const uint4 z4 = make_uint4(0, 0, 0, 0);

    // ldmatrix addresses (byte offsets into smem, stride 144B per row)
    // A frag (16x16): lane 0-15 -> rows m0-15 @k0; lane 16-31 -> same rows @k+8
    int am = lane & 15;
    int ak = (lane >> 4) << 4;     // 0 or 16 bytes
    // B frag x4 (16n x 16k): lane0-7 n0-7@k0, 8-15 n0-7@k8, 16-23 n8-15@k0, 24-31 n8-15@k8
    int bn = (lane & 7) + ((lane & 16) ? 8 : 0);
    int bk = (lane & 8) ? 16 : 0;

    for (int c = 0; c < 4; ++c) {
        int k0u = c * 8;           // uint4 offset within 32-uint4 gmem row
        // ---- A tiles: 4 arrays x 128 rows x 8 uint4 ----
        #pragma unroll
        for (int it = 0; it < 4; ++it) {
            int idx = it * 256 + tid;
            int row = idx >> 3, j = idx & 7;
            int grow = bm + row;
            size_t g = (size_t)grow * 32 + k0u + j;
            uint4 a0 = z4, a1 = z4, a2 = z4, a3 = z4;
            if (grow < N_NODES) { a0 = pUhi[g]; a1 = pUlo[g]; a2 = pVhi[g]; a3 = pVlo[g]; }
            int so = row * AST + j * 8;
            *(uint4*)(sm + E_UHI + so) = a0;
            *(uint4*)(sm + E_ULO + so) = a1;
            *(uint4*)(sm + E_VHI + so) = a2;
            *(uint4*)(sm + E_VLO + so) = a3;
        }
        // ---- B tiles: 4 arrays x 64 rows x 8 uint4 ----
        #pragma unroll
        for (int it = 0; it < 2; ++it) {
            int idx = it * 256 + tid;
            int row = idx >> 3, j = idx & 7;
            size_t g = (size_t)(n0g + row) * 32 + k0u + j;
            int so = row * AST + j * 8;
            *(uint4*)(sm + E_W1H + so) = pW1h[g];
            *(uint4*)(sm + E_W1L + so) = pW1l[g];
            *(uint4*)(sm + E_W2H + so) = pW2h[g];
            *(uint4*)(sm + E_W2L + so) = pW2l[g];
        }
        __syncthreads();

        #pragma unroll
        for (int ks = 0; ks < 4; ++ks) {
            int kb = ks * 32;      // byte offset of k16 step
            // ---------- GEMM 1: U x W1 ----------
            {
                uint32_t ah[2][4], al[2][4];
                #pragma unroll
                for (int mt = 0; mt < 2; mt++) {
                    int m = warp_m * 32 + mt * 16 + am;
                    uint32_t ao = m * 144 + kb + ak;
                    ldsm_x4(ah[mt], sb + E_UHI * 2 + ao);
                    ldsm_x4(al[mt], sb + E_ULO * 2 + ao);
                }
                uint32_t bh[4][2], bl[4][2];
                #pragma unroll
                for (int np = 0; np < 2; np++) {
                    int n = warp_n * 32 + np * 16 + bn;
                    uint32_t bo = n * 144 + kb + bk;
                    uint32_t t[4];
                    ldsm_x4(t, sb + E_W1H * 2 + bo);
                    bh[2*np][0] = t[0]; bh[2*np][1] = t[1];
                    bh[2*np+1][0] = t[2]; bh[2*np+1][1] = t[3];
                    ldsm_x4(t, sb + E_W1L * 2 + bo);
                    bl[2*np][0] = t[0]; bl[2*np][1] = t[1];
                    bl[2*np+1][0] = t[2]; bl[2*np+1][1] = t[3];
                }
                #pragma unroll
                for (int mt = 0; mt < 2; mt++)
                    #pragma unroll
                    for (int nt = 0; nt < 4; nt++) {
                        mma16816(acc1[mt][nt], ah[mt], bh[nt]);
                        mma16816(acc1[mt][nt], ah[mt], bl[nt]);
                        mma16816(acc1[mt][nt], al[mt], bh[nt]);
                    }
            }
            // ---------- GEMM 2: V x W2 ----------
            {
                uint32_t ah[2][4], al[2][4];
                #pragma unroll
                for (int mt = 0; mt < 2; mt++) {
                    int m = warp_m * 32 + mt * 16 + am;
                    uint32_t ao = m * 144 + kb + ak;
                    ldsm_x4(ah[mt], sb + E_VHI * 2 + ao);
                    ldsm_x4(al[mt], sb + E_VLO * 2 + ao);
                }
                uint32_t bh[4][2], bl[4][2];
                #pragma unroll
                for (int np = 0; np < 2; np++) {
                    int n = warp_n * 32 + np * 16 + bn;
                    uint32_t bo = n * 144 + kb + bk;
                    uint32_t t[4];
                    ldsm_x4(t, sb + E_W2H * 2 + bo);
                    bh[2*np][0] = t[0]; bh[2*np][1] = t[1];
                    bh[2*np+1][0] = t[2]; bh[2*np+1][1] = t[3];
                    ldsm_x4(t, sb + E_W2L * 2 + bo);
                    bl[2*np][0] = t[0]; bl[2*np][1] = t[1];
                    bl[2*np+1][0] = t[2]; bl[2*np+1][1] = t[3];
                }
                #pragma unroll
                for (int mt = 0; mt < 2; mt++)
                    #pragma unroll
                    for (int nt = 0; nt < 4; nt++) {
                        mma16816(acc2[mt][nt], ah[mt], bh[nt]);
                        mma16816(acc2[mt][nt], ah[mt], bl[nt]);
                        mma16816(acc2[mt][nt], al[mt], bh[nt]);
                    }
            }
        }
        __syncthreads();
    }

    // ---- epilogue ----
    // thread (mt,nt): c0,c1 -> (row, col..col+1); c2,c3 -> (row+8, col..col+1)
    int rbase = bm + warp_m * 32 + (lane >> 2);
    int cbase = n0g + warp_n * 32 + (lane & 3) * 2;
    #pragma unroll
    for (int mt = 0; mt < 2; mt++) {
        #pragma unroll
        for (int nt = 0; nt < 4; nt++) {
            int col = cbase + nt * 8;
            float bb1x = __ldg(&b1[col]), bb1y = __ldg(&b1[col + 1]);
            float bb2x = __ldg(&b2[col]), bb2y = __ldg(&b2[col + 1]);
            #pragma unroll
            for (int h = 0; h < 2; h++) {           // h=0: row, h=1: row+8
                int row = rbase + mt * 16 + h * 8;
                if (row < N_NODES) {
                    float x1 = acc1[mt][nt][2*h + 0] + bb1x;
                    float y1 = acc1[mt][nt][2*h + 1] + bb1y;
                    float x2 = acc2[mt][nt][2*h + 0] + bb2x;
                    float y2 = acc2[mt][nt][2*h + 1] + bb2y;
                    x1 = fmaxf(x1, NEG_SLOPE * x1);
                    y1 = fmaxf(y1, NEG_SLOPE * y1);
                    x2 = fmaxf(x2, NEG_SLOPE * x2);
                    y2 = fmaxf(y2, NEG_SLOPE * y2);
                    float2 o = make_float2(x1 + x2, y1 + y2);
                    *(float2*)&out[(size_t)row * D + col] = o;
                }
            }
        }
    }
}

// ================= launch =================
extern "C" void kernel_launch(void* const* d_in, const int* in_sizes, int n_in,
                              void* d_out, int out_size) {
    const float* ego  = (const float*)d_in[0];
    const float* vals = (const float*)d_in[1];
    const float* W1   = (const float*)d_in[2];
    const float* b1   = (const float*)d_in[3];
    const float* W2   = (const float*)d_in[4];
    const float* b2   = (const float*)d_in[5];
    const int*   rows = (const int*)d_in[6];
    const int*   cols = (const int*)d_in[7];
    float*       out  = (float*)d_out;

    cudaFuncSetAttribute(k_gemm_mma, cudaFuncAttributeMaxDynamicSharedMemorySize, SMEM_BYTES);

    k_zero_cnt<<<(N_NODES + 255) / 256, 256>>>();
    k_hist<<<(N_EDGES + 255) / 256, 256>>>(rows);
    k_scan<<<1, 1024>>>();
    k_scatter<<<(N_EDGES + 255) / 256, 256>>>(rows, cols, vals);
    k_wprep<<<256, 256>>>(W1, W2);
    k_spmm<<<N_NODES, 256>>>(ego);

    dim3 grid(4, (N_NODES + 127) / 128);   // n-block fastest => A reuse in L2
    k_gemm_mma<<<grid, 256, SMEM_BYTES>>>(b1, b2, out);
}

// round 6
// speedup vs baseline: 2.0849x; 1.3773x over previous
#include <cuda_runtime.h>
#include <cuda_bf16.h>
#include <cstdint>

#define N_NODES 100000
#define N_EDGES 1600000
#define D 256
#define NEG_SLOPE 0.01f

// ================= device scratch =================
__device__ int   g_cnt[N_NODES];
__device__ int   g_off[N_NODES + 1];
__device__ int   g_cur[N_NODES];
__device__ int   g_scol[N_EDGES];
__device__ float g_sval[N_EDGES];
// bf16 hi/lo splits of U = ego+side, V = ego*side   [N_NODES][256] row-major
__device__ __nv_bfloat16 g_uhi[(size_t)N_NODES * D];
__device__ __nv_bfloat16 g_ulo[(size_t)N_NODES * D];
__device__ __nv_bfloat16 g_vhi[(size_t)N_NODES * D];
__device__ __nv_bfloat16 g_vlo[(size_t)N_NODES * D];
// W^T hi/lo splits, [n][k] row-major (k contiguous)
__device__ __nv_bfloat16 g_w1hi[D * D];
__device__ __nv_bfloat16 g_w1lo[D * D];
__device__ __nv_bfloat16 g_w2hi[D * D];
__device__ __nv_bfloat16 g_w2lo[D * D];

// ================= sort phase =================
__global__ void k_zero_cnt() {
    int i = blockIdx.x * blockDim.x + threadIdx.x;
    if (i < N_NODES) g_cnt[i] = 0;
}
__global__ void k_hist(const int* __restrict__ rows) {
    int e = blockIdx.x * blockDim.x + threadIdx.x;
    if (e < N_EDGES) atomicAdd(&g_cnt[rows[e]], 1);
}
__global__ void k_scan() {
    __shared__ int warp_sums[32];
    __shared__ int s_carry;
    const int T = 1024;
    int tid = threadIdx.x, lane = tid & 31, wid = tid >> 5;
    if (tid == 0) s_carry = 0;
    __syncthreads();
    for (int base = 0; base < N_NODES; base += T) {
        int idx = base + tid;
        int x = (idx < N_NODES) ? g_cnt[idx] : 0;
        int v = x;
        #pragma unroll
        for (int off = 1; off < 32; off <<= 1) {
            int t = __shfl_up_sync(0xFFFFFFFFu, v, off);
            if (lane >= off) v += t;
        }
        if (lane == 31) warp_sums[wid] = v;
        __syncthreads();
        if (wid == 0) {
            int w = warp_sums[lane];
            #pragma unroll
            for (int off = 1; off < 32; off <<= 1) {
                int t = __shfl_up_sync(0xFFFFFFFFu, w, off);
                if (lane >= off) w += t;
            }
            warp_sums[lane] = w;
        }
        __syncthreads();
        int carry = s_carry;
        int warp_prefix = (wid > 0) ? warp_sums[wid - 1] : 0;
        int incl = v + warp_prefix;
        int excl = incl - x + carry;
        if (idx < N_NODES) { g_off[idx] = excl; g_cur[idx] = excl; }
        __syncthreads();
        if (tid == T - 1) s_carry = carry + incl;
        __syncthreads();
    }
    if (tid == 0) g_off[N_NODES] = s_carry;
}
__global__ void k_scatter(const int* __restrict__ rows, const int* __restrict__ cols,
                          const float* __restrict__ vals) {
    int e = blockIdx.x * blockDim.x + threadIdx.x;
    if (e < N_EDGES) {
        int r = rows[e];
        int p = atomicAdd(&g_cur[r], 1);
        g_scol[p] = cols[e];
        g_sval[p] = vals[e];
    }
}

// ================= SpMM (warp-per-row) + bi-interaction + bf16 split =================
__device__ __forceinline__ uint32_t pack_bf2(float a, float b) {
    __nv_bfloat162 h = __floats2bfloat162_rn(a, b);
    return *(uint32_t*)&h;
}
__device__ __forceinline__ float bf16rt(float x) {      // round-trip through bf16
    return __bfloat162float(__float2bfloat16(x));
}

__global__ __launch_bounds__(256) void k_spmm(const float* __restrict__ ego) {
    int gw = (blockIdx.x * 256 + threadIdx.x) >> 5;     // one warp per row
    if (gw >= N_NODES) return;
    int lane = threadIdx.x & 31;
    int beg = g_off[gw], end = g_off[gw + 1];
    const float4* __restrict__ egod = (const float4*)ego;
    size_t l2 = (size_t)lane * 2;                       // float4 index within row (64/row)

    float4 acc0 = make_float4(0.f, 0.f, 0.f, 0.f);
    float4 acc1 = make_float4(0.f, 0.f, 0.f, 0.f);

    int i = beg;
    for (; i + 1 < end; i += 2) {
        int   ca = g_scol[i],     cb = g_scol[i + 1];
        float va = g_sval[i],     vb = g_sval[i + 1];
        size_t ba = (size_t)ca * 64 + l2;
        size_t bb = (size_t)cb * 64 + l2;
        float4 A0 = __ldg(&egod[ba]);
        float4 A1 = __ldg(&egod[ba + 1]);
        float4 B0 = __ldg(&egod[bb]);
        float4 B1 = __ldg(&egod[bb + 1]);
        acc0.x = fmaf(va, A0.x, acc0.x); acc0.y = fmaf(va, A0.y, acc0.y);
        acc0.z = fmaf(va, A0.z, acc0.z); acc0.w = fmaf(va, A0.w, acc0.w);
        acc1.x = fmaf(va, A1.x, acc1.x); acc1.y = fmaf(va, A1.y, acc1.y);
        acc1.z = fmaf(va, A1.z, acc1.z); acc1.w = fmaf(va, A1.w, acc1.w);
        acc0.x = fmaf(vb, B0.x, acc0.x); acc0.y = fmaf(vb, B0.y, acc0.y);
        acc0.z = fmaf(vb, B0.z, acc0.z); acc0.w = fmaf(vb, B0.w, acc0.w);
        acc1.x = fmaf(vb, B1.x, acc1.x); acc1.y = fmaf(vb, B1.y, acc1.y);
        acc1.z = fmaf(vb, B1.z, acc1.z); acc1.w = fmaf(vb, B1.w, acc1.w);
    }
    if (i < end) {
        int   ca = g_scol[i];
        float va = g_sval[i];
        size_t ba = (size_t)ca * 64 + l2;
        float4 A0 = __ldg(&egod[ba]);
        float4 A1 = __ldg(&egod[ba + 1]);
        acc0.x = fmaf(va, A0.x, acc0.x); acc0.y = fmaf(va, A0.y, acc0.y);
        acc0.z = fmaf(va, A0.z, acc0.z); acc0.w = fmaf(va, A0.w, acc0.w);
        acc1.x = fmaf(va, A1.x, acc1.x); acc1.y = fmaf(va, A1.y, acc1.y);
        acc1.z = fmaf(va, A1.z, acc1.z); acc1.w = fmaf(va, A1.w, acc1.w);
    }

    size_t bs = (size_t)gw * 64 + l2;
    float4 E0 = egod[bs], E1 = egod[bs + 1];

    float u[8], v[8];
    u[0] = E0.x + acc0.x; u[1] = E0.y + acc0.y; u[2] = E0.z + acc0.z; u[3] = E0.w + acc0.w;
    u[4] = E1.x + acc1.x; u[5] = E1.y + acc1.y; u[6] = E1.z + acc1.z; u[7] = E1.w + acc1.w;
    v[0] = E0.x * acc0.x; v[1] = E0.y * acc0.y; v[2] = E0.z * acc0.z; v[3] = E0.w * acc0.w;
    v[4] = E1.x * acc1.x; v[5] = E1.y * acc1.y; v[6] = E1.z * acc1.z; v[7] = E1.w * acc1.w;

    uint4 uh, ul, vh, vl;
    uh.x = pack_bf2(u[0], u[1]); uh.y = pack_bf2(u[2], u[3]);
    uh.z = pack_bf2(u[4], u[5]); uh.w = pack_bf2(u[6], u[7]);
    ul.x = pack_bf2(u[0] - bf16rt(u[0]), u[1] - bf16rt(u[1]));
    ul.y = pack_bf2(u[2] - bf16rt(u[2]), u[3] - bf16rt(u[3]));
    ul.z = pack_bf2(u[4] - bf16rt(u[4]), u[5] - bf16rt(u[5]));
    ul.w = pack_bf2(u[6] - bf16rt(u[6]), u[7] - bf16rt(u[7]));
    vh.x = pack_bf2(v[0], v[1]); vh.y = pack_bf2(v[2], v[3]);
    vh.z = pack_bf2(v[4], v[5]); vh.w = pack_bf2(v[6], v[7]);
    vl.x = pack_bf2(v[0] - bf16rt(v[0]), v[1] - bf16rt(v[1]));
    vl.y = pack_bf2(v[2] - bf16rt(v[2]), v[3] - bf16rt(v[3]));
    vl.z = pack_bf2(v[4] - bf16rt(v[4]), v[5] - bf16rt(v[5]));
    vl.w = pack_bf2(v[6] - bf16rt(v[6]), v[7] - bf16rt(v[7]));

    size_t o4 = (size_t)gw * 16 + lane / 2 * 2 + (lane & 1);   // uint4 index = gw*16 + lane/2*... 
    // NOTE: each lane owns bf16 elems [lane*8, lane*8+8) = 16 bytes = uint4 index gw*16 + lane/2? 
    // lane*8 bf16 = lane*16 bytes -> uint4 index = gw*16 + lane. (256 bf16 = 512B = 32 uint4? No:
    // 256 bf16 = 512 B = 32 uint4 per row.) Correct: row has 32 uint4; lane owns index lane.
    o4 = (size_t)gw * 32 + lane * 16 / 16;   // = gw*32 + lane
    ((uint4*)g_uhi)[(size_t)gw * 32 + lane] = uh;
    ((uint4*)g_ulo)[(size_t)gw * 32 + lane] = ul;
    ((uint4*)g_vhi)[(size_t)gw * 32 + lane] = vh;
    ((uint4*)g_vlo)[(size_t)gw * 32 + lane] = vl;
}

// ================= W transpose + split: g_w*[n][k] =================
__global__ void k_wprep(const float* __restrict__ W1, const float* __restrict__ W2) {
    int idx = blockIdx.x * blockDim.x + threadIdx.x;   // 65536
    int n = idx & 255, k = idx >> 8;
    float w1 = W1[k * D + n];
    float w2 = W2[k * D + n];
    __nv_bfloat16 h1 = __float2bfloat16(w1);
    __nv_bfloat16 h2 = __float2bfloat16(w2);
    int o = n * D + k;
    g_w1hi[o] = h1; g_w1lo[o] = __float2bfloat16(w1 - __bfloat162float(h1));
    g_w2hi[o] = h2; g_w2lo[o] = __float2bfloat16(w2 - __bfloat162float(h2));
}

// ================= mma.sync helpers =================
__device__ __forceinline__ uint32_t smem_u32(const void* p) {
    uint32_t a;
    asm("{ .reg .u64 t; cvta.to.shared.u64 t, %1; cvt.u32.u64 %0, t; }" : "=r"(a) : "l"(p));
    return a;
}
__device__ __forceinline__ void ldsm_x4(uint32_t* r, uint32_t addr) {
    asm volatile("ldmatrix.sync.aligned.m8n8.x4.shared.b16 {%0,%1,%2,%3}, [%4];"
        : "=r"(r[0]), "=r"(r[1]), "=r"(r[2]), "=r"(r[3]) : "r"(addr));
}
__device__ __forceinline__ void mma16816(float* d, const uint32_t* a, const uint32_t* b) {
    asm volatile("mma.sync.aligned.m16n8k16.row.col.f32.bf16.bf16.f32 "
        "{%0,%1,%2,%3}, {%4,%5,%6,%7}, {%8,%9}, {%0,%1,%2,%3};"
        : "+f"(d[0]), "+f"(d[1]), "+f"(d[2]), "+f"(d[3])
        : "r"(a[0]), "r"(a[1]), "r"(a[2]), "r"(a[3]), "r"(b[0]), "r"(b[1]));
}

// ================= tensor-core dual GEMM (mma.sync) =================
// CTA: M=128 x N=64. 8 warps = 4(M) x 2(N), warp tile 32x32, K-chunk 32 (8 chunks).
// SMEM 61.4 KB -> 2 CTAs/SM: inter-CTA overlap of load and mma phases.
#define AST 40                                  // bf16 elems per smem row (80 B)
#define E_UHI 0
#define E_ULO (128 * AST)
#define E_VHI (2 * 128 * AST)
#define E_VLO (3 * 128 * AST)
#define E_W1H (4 * 128 * AST)
#define E_W1L (E_W1H + 64 * AST)
#define E_W2H (E_W1H + 2 * 64 * AST)
#define E_W2L (E_W1H + 3 * 64 * AST)
#define SMEM_ELEMS (E_W1H + 4 * 64 * AST)       // 30720 bf16
#define SMEM_BYTES (SMEM_ELEMS * 2)             // 61440 B

__global__ __launch_bounds__(256, 2) void k_gemm_mma(
    const float* __restrict__ b1, const float* __restrict__ b2,
    float* __restrict__ out)
{
    extern __shared__ __nv_bfloat16 sm[];
    uint32_t sb = smem_u32(sm);

    int tid = threadIdx.x;
    int lane = tid & 31;
    int wid = tid >> 5;
    int warp_m = wid >> 1;         // 0..3
    int warp_n = wid & 1;          // 0..1
    int bm = blockIdx.y * 128;
    int n0g = blockIdx.x * 64;

    float acc1[2][4][4], acc2[2][4][4];
    #pragma unroll
    for (int mt = 0; mt < 2; mt++)
        #pragma unroll
        for (int nt = 0; nt < 4; nt++)
            #pragma unroll
            for (int q = 0; q < 4; q++) { acc1[mt][nt][q] = 0.f; acc2[mt][nt][q] = 0.f; }

    const uint4* pUhi = (const uint4*)g_uhi;
    const uint4* pUlo = (const uint4*)g_ulo;
    const uint4* pVhi = (const uint4*)g_vhi;
    const uint4* pVlo = (const uint4*)g_vlo;
    const uint4* pW1h = (const uint4*)g_w1hi;
    const uint4* pW1l = (const uint4*)g_w1lo;
    const uint4* pW2h = (const uint4*)g_w2hi;
    const uint4* pW2l = (const uint4*)g_w2lo;
    const uint4 z4 = make_uint4(0, 0, 0, 0);

    // ldmatrix lane->address components (byte stride 80 per row)
    int am = lane & 15;
    int ak = (lane >> 4) << 4;     // 0 or 16 bytes
    int bn = (lane & 7) + ((lane & 16) ? 8 : 0);
    int bk = (lane & 8) ? 16 : 0;

    for (int c = 0; c < 8; ++c) {
        int k0u = c * 4;           // uint4 offset within 32-uint4 gmem row
        // ---- A tiles: 4 arrays x 128 rows x 4 uint4 (2 iters of 256 threads) ----
        #pragma unroll
        for (int it = 0; it < 2; ++it) {
            int idx = it * 256 + tid;
            int row = idx >> 2, j = idx & 3;
            int grow = bm + row;
            size_t g = (size_t)grow * 32 + k0u + j;
            uint4 a0 = z4, a1 = z4, a2 = z4, a3 = z4;
            if (grow < N_NODES) { a0 = pUhi[g]; a1 = pUlo[g]; a2 = pVhi[g]; a3 = pVlo[g]; }
            int so = row * AST + j * 8;
            *(uint4*)(sm + E_UHI + so) = a0;
            *(uint4*)(sm + E_ULO + so) = a1;
            *(uint4*)(sm + E_VHI + so) = a2;
            *(uint4*)(sm + E_VLO + so) = a3;
        }
        // ---- B tiles: 4 arrays x 64 rows x 4 uint4 (1 iter) ----
        {
            int row = tid >> 2, j = tid & 3;
            size_t g = (size_t)(n0g + row) * 32 + k0u + j;
            int so = row * AST + j * 8;
            *(uint4*)(sm + E_W1H + so) = pW1h[g];
            *(uint4*)(sm + E_W1L + so) = pW1l[g];
            *(uint4*)(sm + E_W2H + so) = pW2h[g];
            *(uint4*)(sm + E_W2L + so) = pW2l[g];
        }
        __syncthreads();

        #pragma unroll
        for (int ks = 0; ks < 2; ++ks) {
            int kb = ks * 32;      // byte offset of k16 step
            // ---------- GEMM 1: U x W1 ----------
            {
                uint32_t ah[2][4], al[2][4];
                #pragma unroll
                for (int mt = 0; mt < 2; mt++) {
                    int m = warp_m * 32 + mt * 16 + am;
                    uint32_t ao = m * 80 + kb + ak;
                    ldsm_x4(ah[mt], sb + E_UHI * 2 + ao);
                    ldsm_x4(al[mt], sb + E_ULO * 2 + ao);
                }
                uint32_t bh[4][2], bl[4][2];
                #pragma unroll
                for (int np = 0; np < 2; np++) {
                    int n = warp_n * 32 + np * 16 + bn;
                    uint32_t bo = n * 80 + kb + bk;
                    uint32_t t[4];
                    ldsm_x4(t, sb + E_W1H * 2 + bo);
                    bh[2*np][0] = t[0]; bh[2*np][1] = t[1];
                    bh[2*np+1][0] = t[2]; bh[2*np+1][1] = t[3];
                    ldsm_x4(t, sb + E_W1L * 2 + bo);
                    bl[2*np][0] = t[0]; bl[2*np][1] = t[1];
                    bl[2*np+1][0] = t[2]; bl[2*np+1][1] = t[3];
                }
                #pragma unroll
                for (int mt = 0; mt < 2; mt++)
                    #pragma unroll
                    for (int nt = 0; nt < 4; nt++) {
                        mma16816(acc1[mt][nt], ah[mt], bh[nt]);
                        mma16816(acc1[mt][nt], ah[mt], bl[nt]);
                        mma16816(acc1[mt][nt], al[mt], bh[nt]);
                    }
            }
            // ---------- GEMM 2: V x W2 ----------
            {
                uint32_t ah[2][4], al[2][4];
                #pragma unroll
                for (int mt = 0; mt < 2; mt++) {
                    int m = warp_m * 32 + mt * 16 + am;
                    uint32_t ao = m * 80 + kb + ak;
                    ldsm_x4(ah[mt], sb + E_VHI * 2 + ao);
                    ldsm_x4(al[mt], sb + E_VLO * 2 + ao);
                }
                uint32_t bh[4][2], bl[4][2];
                #pragma unroll
                for (int np = 0; np < 2; np++) {
                    int n = warp_n * 32 + np * 16 + bn;
                    uint32_t bo = n * 80 + kb + bk;
                    uint32_t t[4];
                    ldsm_x4(t, sb + E_W2H * 2 + bo);
                    bh[2*np][0] = t[0]; bh[2*np][1] = t[1];
                    bh[2*np+1][0] = t[2]; bh[2*np+1][1] = t[3];
                    ldsm_x4(t, sb + E_W2L * 2 + bo);
                    bl[2*np][0] = t[0]; bl[2*np][1] = t[1];
                    bl[2*np+1][0] = t[2]; bl[2*np+1][1] = t[3];
                }
                #pragma unroll
                for (int mt = 0; mt < 2; mt++)
                    #pragma unroll
                    for (int nt = 0; nt < 4; nt++) {
                        mma16816(acc2[mt][nt], ah[mt], bh[nt]);
                        mma16816(acc2[mt][nt], ah[mt], bl[nt]);
                        mma16816(acc2[mt][nt], al[mt], bh[nt]);
                    }
            }
        }
        __syncthreads();
    }

    // ---- epilogue ----
    int rbase = bm + warp_m * 32 + (lane >> 2);
    int cbase = n0g + warp_n * 32 + (lane & 3) * 2;
    #pragma unroll
    for (int mt = 0; mt < 2; mt++) {
        #pragma unroll
        for (int nt = 0; nt < 4; nt++) {
            int col = cbase + nt * 8;
            float bb1x = __ldg(&b1[col]), bb1y = __ldg(&b1[col + 1]);
            float bb2x = __ldg(&b2[col]), bb2y = __ldg(&b2[col + 1]);
            #pragma unroll
            for (int h = 0; h < 2; h++) {
                int row = rbase + mt * 16 + h * 8;
                if (row < N_NODES) {
                    float x1 = acc1[mt][nt][2*h + 0] + bb1x;
                    float y1 = acc1[mt][nt][2*h + 1] + bb1y;
                    float x2 = acc2[mt][nt][2*h + 0] + bb2x;
                    float y2 = acc2[mt][nt][2*h + 1] + bb2y;
                    x1 = fmaxf(x1, NEG_SLOPE * x1);
                    y1 = fmaxf(y1, NEG_SLOPE * y1);
                    x2 = fmaxf(x2, NEG_SLOPE * x2);
                    y2 = fmaxf(y2, NEG_SLOPE * y2);
                    float2 o = make_float2(x1 + x2, y1 + y2);
                    *(float2*)&out[(size_t)row * D + col] = o;
                }
            }
        }
    }
}

// ================= launch =================
extern "C" void kernel_launch(void* const* d_in, const int* in_sizes, int n_in,
                              void* d_out, int out_size) {
    const float* ego  = (const float*)d_in[0];
    const float* vals = (const float*)d_in[1];
    const float* W1   = (const float*)d_in[2];
    const float* b1   = (const float*)d_in[3];
    const float* W2   = (const float*)d_in[4];
    const float* b2   = (const float*)d_in[5];
    const int*   rows = (const int*)d_in[6];
    const int*   cols = (const int*)d_in[7];
    float*       out  = (float*)d_out;

    cudaFuncSetAttribute(k_gemm_mma, cudaFuncAttributeMaxDynamicSharedMemorySize, SMEM_BYTES);

    k_zero_cnt<<<(N_NODES + 255) / 256, 256>>>();
    k_hist<<<(N_EDGES + 255) / 256, 256>>>(rows);
    k_scan<<<1, 1024>>>();
    k_scatter<<<(N_EDGES + 255) / 256, 256>>>(rows, cols, vals);
    k_wprep<<<256, 256>>>(W1, W2);

    int spmm_blocks = (N_NODES * 32 + 255) / 256;   // one warp per row
    k_spmm<<<spmm_blocks, 256>>>(ego);

    dim3 grid(4, (N_NODES + 127) / 128);   // n-block fastest => A reuse in L2
    k_gemm_mma<<<grid, 256, SMEM_BYTES>>>(b1, b2, out);
}